// round 13
// baseline (speedup 1.0000x reference)
#include <cuda_runtime.h>
#include <cuda_fp16.h>
#include <cstdint>

#define NN 40000
#define EE 640000
#define GG 2048
#define DD 128
#define LL 5

// ================= PTX helpers =================
__device__ __forceinline__ uint32_t smem_u32(const void* p) {
    uint32_t a;
    asm("{ .reg .u64 t; cvta.to.shared.u64 t, %1; cvt.u32.u64 %0, t; }" : "=r"(a) : "l"(p));
    return a;
}
__device__ __forceinline__ void ldsm_x4(uint32_t addr, uint32_t& r0, uint32_t& r1,
                                        uint32_t& r2, uint32_t& r3) {
    asm volatile("ldmatrix.sync.aligned.m8n8.x4.shared.b16 {%0,%1,%2,%3}, [%4];"
                 : "=r"(r0), "=r"(r1), "=r"(r2), "=r"(r3) : "r"(addr));
}
__device__ __forceinline__ void mma16816f(float* d, const uint32_t* a, const uint32_t* b) {
    asm volatile(
        "mma.sync.aligned.m16n8k16.row.col.f32.f16.f16.f32 "
        "{%0,%1,%2,%3}, {%4,%5,%6,%7}, {%8,%9}, {%0,%1,%2,%3};"
        : "+f"(d[0]), "+f"(d[1]), "+f"(d[2]), "+f"(d[3])
        : "r"(a[0]), "r"(a[1]), "r"(a[2]), "r"(a[3]), "r"(b[0]), "r"(b[1]));
}
__device__ __forceinline__ void cpa16(uint32_t dst, const void* src) {
    asm volatile("cp.async.cg.shared.global [%0], [%1], 16;"
                 :: "r"(dst), "l"(src));
}
#define CP_COMMIT asm volatile("cp.async.commit_group;" ::: "memory")
#define CP_WAIT(n) asm volatile("cp.async.wait_group %0;" :: "n"(n) : "memory")

// ================= device scratch =================
__device__ __align__(16) float   g_X[NN * DD];          // fp32 (self term + pool)
__device__ __align__(16) __half  g_Xf16[NN * DD];       // fp16 copy for gather
__device__ __align__(16) __half  g_Hf[NN * DD];         // MLP input (fp16)
__device__ __align__(16) __half  g_etab_h[LL * 512 * DD];
__device__ int   g_rowptr[NN + 1];
__device__ int   g_deg[NN];
__device__ int   g_cursor[NN];
__device__ int   g_csr[EE];
__device__ __align__(16) __half  g_w1f[LL * 256 * 128];
__device__ __align__(16) __half  g_w2f[LL * 2 * 128 * 128];

// ================= CSR construction =================
__global__ void k_zero() {
    int i = blockIdx.x * blockDim.x + threadIdx.x;
    if (i < NN) { g_deg[i] = 0; g_cursor[i] = 0; }
}
__global__ void k_count(const int* __restrict__ eidx) {
    int e = blockIdx.x * blockDim.x + threadIdx.x;
    if (e < EE) atomicAdd(&g_deg[eidx[EE + e]], 1);
}
__global__ void k_scan() {
    __shared__ int warp_sums[32];
    __shared__ int s_carry;
    int tid = threadIdx.x;
    if (tid == 0) { s_carry = 0; g_rowptr[0] = 0; }
    __syncthreads();
    int lane = tid & 31, w = tid >> 5;
    for (int base = 0; base < NN; base += 1024) {
        int i = base + tid;
        int v = (i < NN) ? g_deg[i] : 0;
        int x = v;
        #pragma unroll
        for (int o = 1; o < 32; o <<= 1) {
            int y = __shfl_up_sync(0xFFFFFFFFu, x, o);
            if (lane >= o) x += y;
        }
        if (lane == 31) warp_sums[w] = x;
        __syncthreads();
        if (w == 0) {
            int s = warp_sums[lane];
            #pragma unroll
            for (int o = 1; o < 32; o <<= 1) {
                int y = __shfl_up_sync(0xFFFFFFFFu, s, o);
                if (lane >= o) s += y;
            }
            warp_sums[lane] = s;
        }
        __syncthreads();
        int incl = x + (w > 0 ? warp_sums[w - 1] : 0) + s_carry;
        if (i < NN) g_rowptr[i + 1] = incl;
        __syncthreads();
        if (tid == 1023) s_carry = incl;
        __syncthreads();
    }
}
__global__ void k_fill(const int* __restrict__ eidx, const int* __restrict__ eattr) {
    int e = blockIdx.x * blockDim.x + threadIdx.x;
    if (e < EE) {
        int d = eidx[EE + e];
        int pos = atomicAdd(&g_cursor[d], 1);
        int s = eidx[e];
        int code = eattr[e * 3] | (eattr[e * 3 + 1] << 3) | (eattr[e * 3 + 2] << 6);
        g_csr[g_rowptr[d] + pos] = s | (code << 16);
    }
}

// ================= atom encoder =================
__global__ void k_atom(const int* __restrict__ xa, const float* __restrict__ aemb) {
    int node = blockIdx.x * 2 + (threadIdx.x >> 7);
    int d = threadIdx.x & 127;
    float s = 0.f;
    #pragma unroll
    for (int f = 0; f < 9; ++f) {
        int idx = xa[node * 9 + f];
        s += aemb[(f * 64 + idx) * DD + d];
    }
    g_X[node * DD + d] = s;
    g_Xf16[node * DD + d] = __float2half_rn(s);
}

// ================= bond-embedding code tables (all layers, fp16) ============
__global__ void k_etab_all(const float* __restrict__ bemb) {
    int c = blockIdx.x & 511;
    int lay = blockIdx.x >> 9;
    int d = threadIdx.x;
    const float* b = bemb + (size_t)lay * 3 * 8 * DD;
    float s = 0.f;
    #pragma unroll
    for (int f = 0; f < 3; ++f) {
        int idx = (c >> (3 * f)) & 7;
        s += b[(f * 8 + idx) * DD + d];
    }
    g_etab_h[((size_t)lay * 512 + c) * DD + d] = __float2half_rn(s);
}

// ================= weight transpose to fp16 [n][k] =================
__global__ void k_wconv1(const float* __restrict__ W1) {
    int idx = blockIdx.x * 256 + threadIdx.x;
    int e = idx & 32767, l = idx >> 15;
    int n = e >> 7, k = e & 127;
    float v = W1[((size_t)l * 128 + k) * 256 + n];
    g_w1f[(size_t)l * 32768 + n * 128 + k] = __float2half_rn(v);
}
__global__ void k_wconv2(const float* __restrict__ W2) {
    int idx = blockIdx.x * 256 + threadIdx.x;
    int e = idx & 16383, c = (idx >> 14) & 1, l = idx >> 15;
    int n = e >> 7, kk = e & 127;
    float v = W2[((size_t)l * 256 + c * 128 + kk) * 128 + n];
    g_w2f[((size_t)(l * 2 + c)) * 16384 + n * 128 + kk] = __float2half_rn(v);
}

// ================= aggregate: warp/node, 4-way unrolled gather ==============
__global__ void k_agg(const float* __restrict__ epsv, int layer) {
    int node = blockIdx.x * 8 + (threadIdx.x >> 5);
    int l = threadIdx.x & 31;
    const float4* __restrict__ X4 = (const float4*)g_X;
    const uint2* __restrict__ XH = (const uint2*)g_Xf16;
    const uint2* __restrict__ E2 = ((const uint2*)g_etab_h) + (size_t)layer * 512 * 32;
    float eps1 = 1.f + epsv[layer];
    float4 xv = X4[node * 32 + l];
    float4 acc = make_float4(xv.x * eps1, xv.y * eps1, xv.z * eps1, xv.w * eps1);
    const __half2 hz = __float2half2_rn(0.f);
    int beg = g_rowptr[node], end = g_rowptr[node + 1];
    int j = beg;
    // 4-way unroll: 8 independent loads in flight, fp16 combine tree
    for (; j + 3 < end; j += 4) {
        int p0 = g_csr[j], p1 = g_csr[j + 1], p2 = g_csr[j + 2], p3 = g_csr[j + 3];
        uint2 x0 = XH[(p0 & 0xFFFF) * 32 + l];
        uint2 x1 = XH[(p1 & 0xFFFF) * 32 + l];
        uint2 x2 = XH[(p2 & 0xFFFF) * 32 + l];
        uint2 x3 = XH[(p3 & 0xFFFF) * 32 + l];
        uint2 e0 = E2[(p0 >> 16) * 32 + l];
        uint2 e1 = E2[(p1 >> 16) * 32 + l];
        uint2 e2 = E2[(p2 >> 16) * 32 + l];
        uint2 e3 = E2[(p3 >> 16) * 32 + l];
        __half2 m0A = __hmax2(__hadd2(*(__half2*)&x0.x, *(__half2*)&e0.x), hz);
        __half2 m0B = __hmax2(__hadd2(*(__half2*)&x0.y, *(__half2*)&e0.y), hz);
        __half2 m1A = __hmax2(__hadd2(*(__half2*)&x1.x, *(__half2*)&e1.x), hz);
        __half2 m1B = __hmax2(__hadd2(*(__half2*)&x1.y, *(__half2*)&e1.y), hz);
        __half2 m2A = __hmax2(__hadd2(*(__half2*)&x2.x, *(__half2*)&e2.x), hz);
        __half2 m2B = __hmax2(__hadd2(*(__half2*)&x2.y, *(__half2*)&e2.y), hz);
        __half2 m3A = __hmax2(__hadd2(*(__half2*)&x3.x, *(__half2*)&e3.x), hz);
        __half2 m3B = __hmax2(__hadd2(*(__half2*)&x3.y, *(__half2*)&e3.y), hz);
        __half2 sA = __hadd2(__hadd2(m0A, m1A), __hadd2(m2A, m3A));
        __half2 sB = __hadd2(__hadd2(m0B, m1B), __hadd2(m2B, m3B));
        float2 fA = __half22float2(sA), fB = __half22float2(sB);
        acc.x += fA.x; acc.y += fA.y; acc.z += fB.x; acc.w += fB.y;
    }
    if (j + 1 < end) {
        int p0 = g_csr[j], p1 = g_csr[j + 1];
        uint2 x0 = XH[(p0 & 0xFFFF) * 32 + l];
        uint2 x1 = XH[(p1 & 0xFFFF) * 32 + l];
        uint2 e0 = E2[(p0 >> 16) * 32 + l];
        uint2 e1 = E2[(p1 >> 16) * 32 + l];
        __half2 m0A = __hmax2(__hadd2(*(__half2*)&x0.x, *(__half2*)&e0.x), hz);
        __half2 m0B = __hmax2(__hadd2(*(__half2*)&x0.y, *(__half2*)&e0.y), hz);
        __half2 m1A = __hmax2(__hadd2(*(__half2*)&x1.x, *(__half2*)&e1.x), hz);
        __half2 m1B = __hmax2(__hadd2(*(__half2*)&x1.y, *(__half2*)&e1.y), hz);
        __half2 sA = __hadd2(m0A, m1A);
        __half2 sB = __hadd2(m0B, m1B);
        float2 fA = __half22float2(sA), fB = __half22float2(sB);
        acc.x += fA.x; acc.y += fA.y; acc.z += fB.x; acc.w += fB.y;
        j += 2;
    }
    if (j < end) {
        int p = g_csr[j];
        uint2 x = XH[(p & 0xFFFF) * 32 + l];
        uint2 e = E2[(p >> 16) * 32 + l];
        __half2 mA = __hmax2(__hadd2(*(__half2*)&x.x, *(__half2*)&e.x), hz);
        __half2 mB = __hmax2(__hadd2(*(__half2*)&x.y, *(__half2*)&e.y), hz);
        float2 fA = __half22float2(mA), fB = __half22float2(mB);
        acc.x += fA.x; acc.y += fA.y; acc.z += fB.x; acc.w += fB.y;
    }
    uint2 outv;
    *(__half2*)&outv.x = __floats2half2_rn(acc.x, acc.y);
    *(__half2*)&outv.y = __floats2half2_rn(acc.z, acc.w);
    ((uint2*)g_Hf)[node * 32 + l] = outv;
}

// ================= fused MLP: H[64x128] -> M[64x256] (smem) -> X[64x128] =====
#define SM_A   0
#define SM_W1  16384
#define SM_M0  81920
#define SM_M1  98304
#define SM_W2A 0
#define SM_W2B 32768
#define MLP_SMEM 114688

__device__ __forceinline__ void stage_tile(const __half* __restrict__ src,
                                           int row0, int nrows, int rowstride,
                                           int k0, uint32_t sdst, int tid) {
    for (int it = tid; it < nrows * 16; it += 256) {
        int r = it >> 4, ci = it & 15;
        size_t gofs = (size_t)(row0 + r) * rowstride + k0 + ci * 8;
        uint32_t off = (uint32_t)(r * 256 + ((ci ^ (r & 7)) << 4));
        cpa16(sdst + off, src + gofs);
    }
}

template<int NJT>
__device__ __forceinline__ void gemm_chunk_f16(
    uint32_t a_base, uint32_t b_base,
    int a_lrow, int a_x7, int a_lci, int b_nrow, int b_x7, int b_lci,
    float (&acc)[2][NJT][4])
{
    #pragma unroll
    for (int s = 0; s < 8; ++s) {
        uint32_t a[2][4], b[NJT][2];
        uint32_t acn = (uint32_t)(((s << 1) | a_lci) ^ a_x7);
        #pragma unroll
        for (int i = 0; i < 2; ++i) {
            uint32_t addr = a_base + (a_lrow + i * 16) * 256 + (acn << 4);
            ldsm_x4(addr, a[i][0], a[i][1], a[i][2], a[i][3]);
        }
        uint32_t bcn = (uint32_t)(((s << 1) | b_lci) ^ b_x7);
        #pragma unroll
        for (int p = 0; p < NJT / 2; ++p) {
            uint32_t addr = b_base + (b_nrow + p * 16) * 256 + (bcn << 4);
            uint32_t r0, r1, r2, r3;
            ldsm_x4(addr, r0, r1, r2, r3);
            b[2 * p][0] = r0; b[2 * p][1] = r1;
            b[2 * p + 1][0] = r2; b[2 * p + 1][1] = r3;
        }
        #pragma unroll
        for (int i = 0; i < 2; ++i)
            #pragma unroll
            for (int j = 0; j < NJT; ++j)
                mma16816f(acc[i][j], a[i], b[j]);
    }
}

__global__ void __launch_bounds__(256, 2) k_mlp(
    int layer,
    const float* __restrict__ b1,  const float* __restrict__ g1,
    const float* __restrict__ bt1, const float* __restrict__ m1,
    const float* __restrict__ v1,
    const float* __restrict__ b2,  const float* __restrict__ gO,
    const float* __restrict__ btO, const float* __restrict__ mO,
    const float* __restrict__ vO,
    int relu_flag)
{
    extern __shared__ char smem[];
    uint32_t sbase = smem_u32(smem);
    int tid = threadIdx.x, lane = tid & 31, wid = tid >> 5;
    int wm = wid >> 2, wn = wid & 3;
    int m0 = blockIdx.x * 64;

    int a_lrow = wm * 32 + (lane & 15);
    int a_x7 = a_lrow & 7;
    int a_lci = lane >> 4;
    int b1_nrow = wn * 64 + ((lane >> 4) << 3) + (lane & 7);
    int b1_x7 = b1_nrow & 7;
    int b1_lci = (lane >> 3) & 1;
    int b2_nrow = wn * 32 + ((lane >> 4) << 3) + (lane & 7);
    int b2_x7 = b2_nrow & 7;
    int b2_lci = (lane >> 3) & 1;

    stage_tile(g_Hf, m0, 64, 128, 0, sbase + SM_A, tid);
    stage_tile(g_w1f + (size_t)layer * 32768, 0, 256, 128, 0, sbase + SM_W1, tid);
    CP_COMMIT;

    float acc1[2][8][4];
    #pragma unroll
    for (int i = 0; i < 2; ++i)
        #pragma unroll
        for (int j = 0; j < 8; ++j)
            #pragma unroll
            for (int q = 0; q < 4; ++q) acc1[i][j][q] = 0.f;

    CP_WAIT(0); __syncthreads();
    gemm_chunk_f16<8>(sbase + SM_A, sbase + SM_W1,
                      a_lrow, a_x7, a_lci, b1_nrow, b1_x7, b1_lci, acc1);
    __syncthreads();

    const __half* wimg2 = g_w2f + (size_t)layer * 2 * 16384;
    stage_tile(wimg2, 0, 128, 128, 0, sbase + SM_W2A, tid);
    stage_tile(wimg2 + 16384, 0, 128, 128, 0, sbase + SM_W2B, tid);
    CP_COMMIT;

    // phase-1 epilogue: bias+BN+ReLU -> fp16 M tiles in smem
    #pragma unroll
    for (int i = 0; i < 2; ++i) {
        int rl0 = wm * 32 + i * 16 + (lane >> 2);
        #pragma unroll
        for (int j = 0; j < 8; ++j) {
            int lc = wn * 64 + j * 8 + (lane & 3) * 2;
            float sc0 = __ldg(&g1[lc])     * rsqrtf(__ldg(&v1[lc]) + 1e-5f);
            float sc1 = __ldg(&g1[lc + 1]) * rsqrtf(__ldg(&v1[lc + 1]) + 1e-5f);
            float sb0 = __ldg(&bt1[lc])     + (__ldg(&b1[lc])     - __ldg(&m1[lc]))     * sc0;
            float sb1 = __ldg(&bt1[lc + 1]) + (__ldg(&b1[lc + 1]) - __ldg(&m1[lc + 1])) * sc1;
            int mbase = (lc >> 7) ? SM_M1 : SM_M0;
            int lcl = lc & 127;
            int ci = lcl >> 3;
            int sub = (lcl & 7) * 2;
            #pragma unroll
            for (int h = 0; h < 2; ++h) {
                int r = rl0 + h * 8;
                float v0 = fmaxf(acc1[i][j][2 * h]     * sc0 + sb0, 0.f);
                float v1v = fmaxf(acc1[i][j][2 * h + 1] * sc1 + sb1, 0.f);
                uint32_t off = (uint32_t)(mbase + r * 256 + ((ci ^ (r & 7)) << 4) + sub);
                *(__half2*)(smem + off) = __floats2half2_rn(v0, v1v);
            }
        }
    }
    CP_WAIT(0); __syncthreads();

    // phase 2: X = M @ W2
    float acc2[2][4][4];
    #pragma unroll
    for (int i = 0; i < 2; ++i)
        #pragma unroll
        for (int j = 0; j < 4; ++j)
            #pragma unroll
            for (int q = 0; q < 4; ++q) acc2[i][j][q] = 0.f;

    gemm_chunk_f16<4>(sbase + SM_M0, sbase + SM_W2A,
                      a_lrow, a_x7, a_lci, b2_nrow, b2_x7, b2_lci, acc2);
    gemm_chunk_f16<4>(sbase + SM_M1, sbase + SM_W2B,
                      a_lrow, a_x7, a_lci, b2_nrow, b2_x7, b2_lci, acc2);

    // phase-2 epilogue -> g_X fp32 + g_Xf16
    #pragma unroll
    for (int i = 0; i < 2; ++i) {
        int row0 = m0 + wm * 32 + i * 16 + (lane >> 2);
        #pragma unroll
        for (int j = 0; j < 4; ++j) {
            int lc = wn * 32 + j * 8 + (lane & 3) * 2;
            float sc0 = __ldg(&gO[lc])     * rsqrtf(__ldg(&vO[lc]) + 1e-5f);
            float sc1 = __ldg(&gO[lc + 1]) * rsqrtf(__ldg(&vO[lc + 1]) + 1e-5f);
            float sb0 = __ldg(&btO[lc])     + (__ldg(&b2[lc])     - __ldg(&mO[lc]))     * sc0;
            float sb1 = __ldg(&btO[lc + 1]) + (__ldg(&b2[lc + 1]) - __ldg(&mO[lc + 1])) * sc1;
            #pragma unroll
            for (int h = 0; h < 2; ++h) {
                int row = row0 + h * 8;
                float v0 = acc2[i][j][2 * h]     * sc0 + sb0;
                float v1v = acc2[i][j][2 * h + 1] * sc1 + sb1;
                if (relu_flag) { v0 = fmaxf(v0, 0.f); v1v = fmaxf(v1v, 0.f); }
                size_t ob = (size_t)row * 128 + lc;
                *(float2*)(g_X + ob) = make_float2(v0, v1v);
                *(__half2*)(g_Xf16 + ob) = __floats2half2_rn(v0, v1v);
            }
        }
    }
}

// ================= pooling + head =================
__device__ __forceinline__ int lb(const int* a, int n, int v) {
    int lo = 0, hi = n;
    while (lo < hi) { int m = (lo + hi) >> 1; if (a[m] < v) lo = m + 1; else hi = m; }
    return lo;
}
__global__ void k_pool(const int* __restrict__ batch,
                       const float* __restrict__ Wp, const float* __restrict__ bp,
                       float* __restrict__ out)
{
    int g = blockIdx.x;
    int lo = lb(batch, NN, g);
    int hi = lb(batch, NN, g + 1);
    int d = threadIdx.x;
    float s = 0.f;
    for (int n = lo; n < hi; ++n) s += g_X[n * DD + d];
    s /= fmaxf((float)(hi - lo), 1.f);
    __shared__ float pooled[DD];
    pooled[d] = s;
    __syncthreads();
    if (d < 10) {
        float o = bp[d];
        #pragma unroll 4
        for (int k = 0; k < DD; ++k) o += pooled[k] * Wp[k * 10 + d];
        out[g * 10 + d] = o;
    }
}

// ================= launch =================
extern "C" void kernel_launch(void* const* d_in, const int* in_sizes, int n_in,
                              void* d_out, int out_size)
{
    const int*   x_atom = (const int*)d_in[0];
    const int*   eidx   = (const int*)d_in[1];
    const int*   eattr  = (const int*)d_in[2];
    const int*   batch  = (const int*)d_in[3];
    const float* aemb   = (const float*)d_in[4];
    const float* bemb   = (const float*)d_in[5];
    const float* eps    = (const float*)d_in[6];
    const float* W1     = (const float*)d_in[7];
    const float* b1     = (const float*)d_in[8];
    const float* g1     = (const float*)d_in[9];
    const float* bt1    = (const float*)d_in[10];
    const float* m1     = (const float*)d_in[11];
    const float* v1     = (const float*)d_in[12];
    const float* W2     = (const float*)d_in[13];
    const float* b2     = (const float*)d_in[14];
    const float* gO     = (const float*)d_in[15];
    const float* btO    = (const float*)d_in[16];
    const float* mO     = (const float*)d_in[17];
    const float* vO     = (const float*)d_in[18];
    const float* Wp     = (const float*)d_in[19];
    const float* bp     = (const float*)d_in[20];
    float* out = (float*)d_out;

    cudaFuncSetAttribute(k_mlp, cudaFuncAttributeMaxDynamicSharedMemorySize, MLP_SMEM);

    k_zero<<<(NN + 255) / 256, 256>>>();
    k_count<<<(EE + 255) / 256, 256>>>(eidx);
    k_scan<<<1, 1024>>>();
    k_fill<<<(EE + 255) / 256, 256>>>(eidx, eattr);
    k_atom<<<NN / 2, 256>>>(x_atom, aemb);
    k_etab_all<<<512 * LL, 128>>>(bemb);
    k_wconv1<<<LL * 32768 / 256, 256>>>(W1);
    k_wconv2<<<LL * 32768 / 256, 256>>>(W2);

    for (int i = 0; i < LL; ++i) {
        k_agg<<<NN / 8, 256>>>(eps, i);
        k_mlp<<<625, 256, MLP_SMEM>>>(i,
            b1 + i * 2 * DD, g1 + i * 2 * DD, bt1 + i * 2 * DD,
            m1 + i * 2 * DD, v1 + i * 2 * DD,
            b2 + i * DD, gO + i * DD, btO + i * DD,
            mO + i * DD, vO + i * DD, (i < LL - 1) ? 1 : 0);
    }

    k_pool<<<GG, 128>>>(batch, Wp, bp, out);
}

// round 14
// speedup vs baseline: 1.4827x; 1.4827x over previous
#include <cuda_runtime.h>
#include <cuda_fp16.h>
#include <cstdint>

#define NN 40000
#define EE 640000
#define GG 2048
#define DD 128
#define LL 5

// ================= PTX helpers =================
__device__ __forceinline__ uint32_t smem_u32(const void* p) {
    uint32_t a;
    asm("{ .reg .u64 t; cvta.to.shared.u64 t, %1; cvt.u32.u64 %0, t; }" : "=r"(a) : "l"(p));
    return a;
}
__device__ __forceinline__ void ldsm_x4(uint32_t addr, uint32_t& r0, uint32_t& r1,
                                        uint32_t& r2, uint32_t& r3) {
    asm volatile("ldmatrix.sync.aligned.m8n8.x4.shared.b16 {%0,%1,%2,%3}, [%4];"
                 : "=r"(r0), "=r"(r1), "=r"(r2), "=r"(r3) : "r"(addr));
}
__device__ __forceinline__ void mma16816f(float* d, const uint32_t* a, const uint32_t* b) {
    asm volatile(
        "mma.sync.aligned.m16n8k16.row.col.f32.f16.f16.f32 "
        "{%0,%1,%2,%3}, {%4,%5,%6,%7}, {%8,%9}, {%0,%1,%2,%3};"
        : "+f"(d[0]), "+f"(d[1]), "+f"(d[2]), "+f"(d[3])
        : "r"(a[0]), "r"(a[1]), "r"(a[2]), "r"(a[3]), "r"(b[0]), "r"(b[1]));
}
__device__ __forceinline__ void cpa16(uint32_t dst, const void* src) {
    asm volatile("cp.async.cg.shared.global [%0], [%1], 16;"
                 :: "r"(dst), "l"(src));
}
#define CP_COMMIT asm volatile("cp.async.commit_group;" ::: "memory")
#define CP_WAIT(n) asm volatile("cp.async.wait_group %0;" :: "n"(n) : "memory")

// ================= device scratch =================
__device__ __align__(16) float   g_X[NN * DD];          // fp32 (self term + pool)
__device__ __align__(16) __half  g_Xf16[NN * DD];       // fp16 copy for gather
__device__ __align__(16) __half  g_Hf[NN * DD];         // MLP input (fp16)
__device__ __align__(16) __half  g_etab_h[LL * 512 * DD];
__device__ int   g_rowptr[NN + 1];
__device__ int   g_deg[NN];
__device__ int   g_cursor[NN];
__device__ int   g_csr[EE];
__device__ __align__(16) __half  g_w1f[LL * 256 * 128];
__device__ __align__(16) __half  g_w2f[LL * 2 * 128 * 128];

// ================= fused preprocessing (zero + atom + etab + wconv) =========
// block ranges: [0,157) zero | [157,20157) atom | [20157,21437) etab (2 codes/blk)
//               [21437,22077) wconv1 | [22077,22717) wconv2
#define PRE_ZERO   157
#define PRE_ATOM   (PRE_ZERO + 20000)
#define PRE_ETAB   (PRE_ATOM + 1280)
#define PRE_W1     (PRE_ETAB + 640)
#define PRE_TOTAL  (PRE_W1 + 640)

__global__ void k_pre(const int* __restrict__ xa, const float* __restrict__ aemb,
                      const float* __restrict__ bemb,
                      const float* __restrict__ W1, const float* __restrict__ W2) {
    int b = blockIdx.x;
    int tid = threadIdx.x;
    if (b < PRE_ZERO) {
        int i = b * 256 + tid;
        if (i < NN) { g_deg[i] = 0; g_cursor[i] = 0; }
    } else if (b < PRE_ATOM) {
        int node = (b - PRE_ZERO) * 2 + (tid >> 7);
        int d = tid & 127;
        float s = 0.f;
        #pragma unroll
        for (int f = 0; f < 9; ++f) {
            int idx = xa[node * 9 + f];
            s += aemb[(f * 64 + idx) * DD + d];
        }
        g_X[node * DD + d] = s;
        g_Xf16[node * DD + d] = __float2half_rn(s);
    } else if (b < PRE_ETAB) {
        int code = (b - PRE_ATOM) * 2 + (tid >> 7);     // 0..2559
        int lay = code >> 9;
        int c = code & 511;
        int d = tid & 127;
        const float* bb = bemb + (size_t)lay * 3 * 8 * DD;
        float s = 0.f;
        #pragma unroll
        for (int f = 0; f < 3; ++f) {
            int idx = (c >> (3 * f)) & 7;
            s += bb[(f * 8 + idx) * DD + d];
        }
        g_etab_h[((size_t)lay * 512 + c) * DD + d] = __float2half_rn(s);
    } else if (b < PRE_W1) {
        int idx = (b - PRE_ETAB) * 256 + tid;           // L*32768
        int e = idx & 32767, l = idx >> 15;
        int n = e >> 7, k = e & 127;
        float v = W1[((size_t)l * 128 + k) * 256 + n];
        g_w1f[(size_t)l * 32768 + n * 128 + k] = __float2half_rn(v);
    } else {
        int idx = (b - PRE_W1) * 256 + tid;
        int e = idx & 16383, c = (idx >> 14) & 1, l = idx >> 15;
        int n = e >> 7, kk = e & 127;
        float v = W2[((size_t)l * 256 + c * 128 + kk) * 128 + n];
        g_w2f[((size_t)(l * 2 + c)) * 16384 + n * 128 + kk] = __float2half_rn(v);
    }
}

// ================= CSR construction =================
__global__ void k_count(const int* __restrict__ eidx) {
    int e = blockIdx.x * blockDim.x + threadIdx.x;
    if (e < EE) atomicAdd(&g_deg[eidx[EE + e]], 1);
}
__global__ void k_scan() {
    __shared__ int warp_sums[32];
    __shared__ int s_carry;
    int tid = threadIdx.x;
    if (tid == 0) { s_carry = 0; g_rowptr[0] = 0; }
    __syncthreads();
    int lane = tid & 31, w = tid >> 5;
    for (int base = 0; base < NN; base += 1024) {
        int i = base + tid;
        int v = (i < NN) ? g_deg[i] : 0;
        int x = v;
        #pragma unroll
        for (int o = 1; o < 32; o <<= 1) {
            int y = __shfl_up_sync(0xFFFFFFFFu, x, o);
            if (lane >= o) x += y;
        }
        if (lane == 31) warp_sums[w] = x;
        __syncthreads();
        if (w == 0) {
            int s = warp_sums[lane];
            #pragma unroll
            for (int o = 1; o < 32; o <<= 1) {
                int y = __shfl_up_sync(0xFFFFFFFFu, s, o);
                if (lane >= o) s += y;
            }
            warp_sums[lane] = s;
        }
        __syncthreads();
        int incl = x + (w > 0 ? warp_sums[w - 1] : 0) + s_carry;
        if (i < NN) g_rowptr[i + 1] = incl;
        __syncthreads();
        if (tid == 1023) s_carry = incl;
        __syncthreads();
    }
}
__global__ void k_fill(const int* __restrict__ eidx, const int* __restrict__ eattr) {
    int e = blockIdx.x * blockDim.x + threadIdx.x;
    if (e < EE) {
        int d = eidx[EE + e];
        int pos = atomicAdd(&g_cursor[d], 1);
        int s = eidx[e];
        int code = eattr[e * 3] | (eattr[e * 3 + 1] << 3) | (eattr[e * 3 + 2] << 6);
        g_csr[g_rowptr[d] + pos] = s | (code << 16);
    }
}

// ================= aggregate: warp/node, pair-combined fp16 messages ========
__global__ void k_agg(const float* __restrict__ epsv, int layer) {
    int node = blockIdx.x * 8 + (threadIdx.x >> 5);
    int l = threadIdx.x & 31;
    const float4* __restrict__ X4 = (const float4*)g_X;
    const uint2* __restrict__ XH = (const uint2*)g_Xf16;
    const uint2* __restrict__ E2 = ((const uint2*)g_etab_h) + (size_t)layer * 512 * 32;
    float eps1 = 1.f + epsv[layer];
    float4 xv = X4[node * 32 + l];
    float4 acc = make_float4(xv.x * eps1, xv.y * eps1, xv.z * eps1, xv.w * eps1);
    const __half2 hz = __float2half2_rn(0.f);
    int beg = g_rowptr[node], end = g_rowptr[node + 1];
    int j = beg;
    for (; j + 1 < end; j += 2) {
        int p0 = g_csr[j], p1 = g_csr[j + 1];
        int s0 = p0 & 0xFFFF, c0 = p0 >> 16;
        int s1 = p1 & 0xFFFF, c1 = p1 >> 16;
        uint2 x0 = XH[s0 * 32 + l];
        uint2 x1 = XH[s1 * 32 + l];
        uint2 e0 = E2[c0 * 32 + l];
        uint2 e1 = E2[c1 * 32 + l];
        __half2 m00 = __hmax2(__hadd2(*(__half2*)&x0.x, *(__half2*)&e0.x), hz);
        __half2 m01 = __hmax2(__hadd2(*(__half2*)&x0.y, *(__half2*)&e0.y), hz);
        __half2 m10 = __hmax2(__hadd2(*(__half2*)&x1.x, *(__half2*)&e1.x), hz);
        __half2 m11 = __hmax2(__hadd2(*(__half2*)&x1.y, *(__half2*)&e1.y), hz);
        __half2 sA = __hadd2(m00, m10);
        __half2 sB = __hadd2(m01, m11);
        float2 fA = __half22float2(sA), fB = __half22float2(sB);
        acc.x += fA.x; acc.y += fA.y; acc.z += fB.x; acc.w += fB.y;
    }
    if (j < end) {
        int p = g_csr[j];
        int s = p & 0xFFFF, c = p >> 16;
        uint2 x = XH[s * 32 + l];
        uint2 e = E2[c * 32 + l];
        __half2 mA = __hmax2(__hadd2(*(__half2*)&x.x, *(__half2*)&e.x), hz);
        __half2 mB = __hmax2(__hadd2(*(__half2*)&x.y, *(__half2*)&e.y), hz);
        float2 fA = __half22float2(mA), fB = __half22float2(mB);
        acc.x += fA.x; acc.y += fA.y; acc.z += fB.x; acc.w += fB.y;
    }
    uint2 outv;
    *(__half2*)&outv.x = __floats2half2_rn(acc.x, acc.y);
    *(__half2*)&outv.y = __floats2half2_rn(acc.z, acc.w);
    ((uint2*)g_Hf)[node * 32 + l] = outv;
}

// ================= fused MLP: H[64x128] -> M[64x256] (smem) -> X[64x128] =====
#define SM_A   0
#define SM_W1  16384
#define SM_M0  81920
#define SM_M1  98304
#define SM_W2A 0
#define SM_W2B 32768
#define MLP_SMEM 114688

__device__ __forceinline__ void stage_tile(const __half* __restrict__ src,
                                           int row0, int nrows, int rowstride,
                                           int k0, uint32_t sdst, int tid) {
    for (int it = tid; it < nrows * 16; it += 256) {
        int r = it >> 4, ci = it & 15;
        size_t gofs = (size_t)(row0 + r) * rowstride + k0 + ci * 8;
        uint32_t off = (uint32_t)(r * 256 + ((ci ^ (r & 7)) << 4));
        cpa16(sdst + off, src + gofs);
    }
}

template<int NJT>
__device__ __forceinline__ void gemm_chunk_f16(
    uint32_t a_base, uint32_t b_base,
    int a_lrow, int a_x7, int a_lci, int b_nrow, int b_x7, int b_lci,
    float (&acc)[2][NJT][4])
{
    #pragma unroll
    for (int s = 0; s < 8; ++s) {
        uint32_t a[2][4], b[NJT][2];
        uint32_t acn = (uint32_t)(((s << 1) | a_lci) ^ a_x7);
        #pragma unroll
        for (int i = 0; i < 2; ++i) {
            uint32_t addr = a_base + (a_lrow + i * 16) * 256 + (acn << 4);
            ldsm_x4(addr, a[i][0], a[i][1], a[i][2], a[i][3]);
        }
        uint32_t bcn = (uint32_t)(((s << 1) | b_lci) ^ b_x7);
        #pragma unroll
        for (int p = 0; p < NJT / 2; ++p) {
            uint32_t addr = b_base + (b_nrow + p * 16) * 256 + (bcn << 4);
            uint32_t r0, r1, r2, r3;
            ldsm_x4(addr, r0, r1, r2, r3);
            b[2 * p][0] = r0; b[2 * p][1] = r1;
            b[2 * p + 1][0] = r2; b[2 * p + 1][1] = r3;
        }
        #pragma unroll
        for (int i = 0; i < 2; ++i)
            #pragma unroll
            for (int j = 0; j < NJT; ++j)
                mma16816f(acc[i][j], a[i], b[j]);
    }
}

__global__ void __launch_bounds__(256, 2) k_mlp(
    int layer,
    const float* __restrict__ b1,  const float* __restrict__ g1,
    const float* __restrict__ bt1, const float* __restrict__ m1,
    const float* __restrict__ v1,
    const float* __restrict__ b2,  const float* __restrict__ gO,
    const float* __restrict__ btO, const float* __restrict__ mO,
    const float* __restrict__ vO,
    int relu_flag)
{
    extern __shared__ char smem[];
    uint32_t sbase = smem_u32(smem);
    int tid = threadIdx.x, lane = tid & 31, wid = tid >> 5;
    int wm = wid >> 2, wn = wid & 3;
    int m0 = blockIdx.x * 64;

    int a_lrow = wm * 32 + (lane & 15);
    int a_x7 = a_lrow & 7;
    int a_lci = lane >> 4;
    int b1_nrow = wn * 64 + ((lane >> 4) << 3) + (lane & 7);
    int b1_x7 = b1_nrow & 7;
    int b1_lci = (lane >> 3) & 1;
    int b2_nrow = wn * 32 + ((lane >> 4) << 3) + (lane & 7);
    int b2_x7 = b2_nrow & 7;
    int b2_lci = (lane >> 3) & 1;

    stage_tile(g_Hf, m0, 64, 128, 0, sbase + SM_A, tid);
    stage_tile(g_w1f + (size_t)layer * 32768, 0, 256, 128, 0, sbase + SM_W1, tid);
    CP_COMMIT;

    float acc1[2][8][4];
    #pragma unroll
    for (int i = 0; i < 2; ++i)
        #pragma unroll
        for (int j = 0; j < 8; ++j)
            #pragma unroll
            for (int q = 0; q < 4; ++q) acc1[i][j][q] = 0.f;

    CP_WAIT(0); __syncthreads();
    gemm_chunk_f16<8>(sbase + SM_A, sbase + SM_W1,
                      a_lrow, a_x7, a_lci, b1_nrow, b1_x7, b1_lci, acc1);
    __syncthreads();

    const __half* wimg2 = g_w2f + (size_t)layer * 2 * 16384;
    stage_tile(wimg2, 0, 128, 128, 0, sbase + SM_W2A, tid);
    stage_tile(wimg2 + 16384, 0, 128, 128, 0, sbase + SM_W2B, tid);
    CP_COMMIT;

    // phase-1 epilogue: bias+BN+ReLU -> fp16 M tiles in smem
    #pragma unroll
    for (int i = 0; i < 2; ++i) {
        int rl0 = wm * 32 + i * 16 + (lane >> 2);
        #pragma unroll
        for (int j = 0; j < 8; ++j) {
            int lc = wn * 64 + j * 8 + (lane & 3) * 2;
            float sc0 = __ldg(&g1[lc])     * rsqrtf(__ldg(&v1[lc]) + 1e-5f);
            float sc1 = __ldg(&g1[lc + 1]) * rsqrtf(__ldg(&v1[lc + 1]) + 1e-5f);
            float sb0 = __ldg(&bt1[lc])     + (__ldg(&b1[lc])     - __ldg(&m1[lc]))     * sc0;
            float sb1 = __ldg(&bt1[lc + 1]) + (__ldg(&b1[lc + 1]) - __ldg(&m1[lc + 1])) * sc1;
            int mbase = (lc >> 7) ? SM_M1 : SM_M0;
            int lcl = lc & 127;
            int ci = lcl >> 3;
            int sub = (lcl & 7) * 2;
            #pragma unroll
            for (int h = 0; h < 2; ++h) {
                int r = rl0 + h * 8;
                float v0 = fmaxf(acc1[i][j][2 * h]     * sc0 + sb0, 0.f);
                float v1v = fmaxf(acc1[i][j][2 * h + 1] * sc1 + sb1, 0.f);
                uint32_t off = (uint32_t)(mbase + r * 256 + ((ci ^ (r & 7)) << 4) + sub);
                *(__half2*)(smem + off) = __floats2half2_rn(v0, v1v);
            }
        }
    }
    CP_WAIT(0); __syncthreads();

    // phase 2: X = M @ W2
    float acc2[2][4][4];
    #pragma unroll
    for (int i = 0; i < 2; ++i)
        #pragma unroll
        for (int j = 0; j < 4; ++j)
            #pragma unroll
            for (int q = 0; q < 4; ++q) acc2[i][j][q] = 0.f;

    gemm_chunk_f16<4>(sbase + SM_M0, sbase + SM_W2A,
                      a_lrow, a_x7, a_lci, b2_nrow, b2_x7, b2_lci, acc2);
    gemm_chunk_f16<4>(sbase + SM_M1, sbase + SM_W2B,
                      a_lrow, a_x7, a_lci, b2_nrow, b2_x7, b2_lci, acc2);

    // phase-2 epilogue -> g_X fp32 + g_Xf16
    #pragma unroll
    for (int i = 0; i < 2; ++i) {
        int row0 = m0 + wm * 32 + i * 16 + (lane >> 2);
        #pragma unroll
        for (int j = 0; j < 4; ++j) {
            int lc = wn * 32 + j * 8 + (lane & 3) * 2;
            float sc0 = __ldg(&gO[lc])     * rsqrtf(__ldg(&vO[lc]) + 1e-5f);
            float sc1 = __ldg(&gO[lc + 1]) * rsqrtf(__ldg(&vO[lc + 1]) + 1e-5f);
            float sb0 = __ldg(&btO[lc])     + (__ldg(&b2[lc])     - __ldg(&mO[lc]))     * sc0;
            float sb1 = __ldg(&btO[lc + 1]) + (__ldg(&b2[lc + 1]) - __ldg(&mO[lc + 1])) * sc1;
            #pragma unroll
            for (int h = 0; h < 2; ++h) {
                int row = row0 + h * 8;
                float v0 = acc2[i][j][2 * h]     * sc0 + sb0;
                float v1v = acc2[i][j][2 * h + 1] * sc1 + sb1;
                if (relu_flag) { v0 = fmaxf(v0, 0.f); v1v = fmaxf(v1v, 0.f); }
                size_t ob = (size_t)row * 128 + lc;
                *(float2*)(g_X + ob) = make_float2(v0, v1v);
                *(__half2*)(g_Xf16 + ob) = __floats2half2_rn(v0, v1v);
            }
        }
    }
}

// ================= pooling + head =================
__device__ __forceinline__ int lb(const int* a, int n, int v) {
    int lo = 0, hi = n;
    while (lo < hi) { int m = (lo + hi) >> 1; if (a[m] < v) lo = m + 1; else hi = m; }
    return lo;
}
__global__ void k_pool(const int* __restrict__ batch,
                       const float* __restrict__ Wp, const float* __restrict__ bp,
                       float* __restrict__ out)
{
    int g = blockIdx.x;
    int lo = lb(batch, NN, g);
    int hi = lb(batch, NN, g + 1);
    int d = threadIdx.x;
    float s = 0.f;
    for (int n = lo; n < hi; ++n) s += g_X[n * DD + d];
    s /= fmaxf((float)(hi - lo), 1.f);
    __shared__ float pooled[DD];
    pooled[d] = s;
    __syncthreads();
    if (d < 10) {
        float o = bp[d];
        #pragma unroll 4
        for (int k = 0; k < DD; ++k) o += pooled[k] * Wp[k * 10 + d];
        out[g * 10 + d] = o;
    }
}

// ================= launch =================
extern "C" void kernel_launch(void* const* d_in, const int* in_sizes, int n_in,
                              void* d_out, int out_size)
{
    const int*   x_atom = (const int*)d_in[0];
    const int*   eidx   = (const int*)d_in[1];
    const int*   eattr  = (const int*)d_in[2];
    const int*   batch  = (const int*)d_in[3];
    const float* aemb   = (const float*)d_in[4];
    const float* bemb   = (const float*)d_in[5];
    const float* eps    = (const float*)d_in[6];
    const float* W1     = (const float*)d_in[7];
    const float* b1     = (const float*)d_in[8];
    const float* g1     = (const float*)d_in[9];
    const float* bt1    = (const float*)d_in[10];
    const float* m1     = (const float*)d_in[11];
    const float* v1     = (const float*)d_in[12];
    const float* W2     = (const float*)d_in[13];
    const float* b2     = (const float*)d_in[14];
    const float* gO     = (const float*)d_in[15];
    const float* btO    = (const float*)d_in[16];
    const float* mO     = (const float*)d_in[17];
    const float* vO     = (const float*)d_in[18];
    const float* Wp     = (const float*)d_in[19];
    const float* bp     = (const float*)d_in[20];
    float* out = (float*)d_out;

    cudaFuncSetAttribute(k_mlp, cudaFuncAttributeMaxDynamicSharedMemorySize, MLP_SMEM);

    k_pre<<<PRE_TOTAL, 256>>>(x_atom, aemb, bemb, W1, W2);
    k_count<<<(EE + 255) / 256, 256>>>(eidx);
    k_scan<<<1, 1024>>>();
    k_fill<<<(EE + 255) / 256, 256>>>(eidx, eattr);

    for (int i = 0; i < LL; ++i) {
        k_agg<<<NN / 8, 256>>>(eps, i);
        k_mlp<<<625, 256, MLP_SMEM>>>(i,
            b1 + i * 2 * DD, g1 + i * 2 * DD, bt1 + i * 2 * DD,
            m1 + i * 2 * DD, v1 + i * 2 * DD,
            b2 + i * DD, gO + i * DD, btO + i * DD,
            mO + i * DD, vO + i * DD, (i < LL - 1) ? 1 : 0);
    }

    k_pool<<<GG, 128>>>(batch, Wp, bp, out);
}

// round 15
// speedup vs baseline: 1.5591x; 1.0515x over previous
#include <cuda_runtime.h>
#include <cuda_fp16.h>
#include <cstdint>

#define NN 40000
#define EE 640000
#define GG 2048
#define DD 128
#define LL 5

// ================= PTX helpers =================
__device__ __forceinline__ uint32_t smem_u32(const void* p) {
    uint32_t a;
    asm("{ .reg .u64 t; cvta.to.shared.u64 t, %1; cvt.u32.u64 %0, t; }" : "=r"(a) : "l"(p));
    return a;
}
__device__ __forceinline__ void ldsm_x4(uint32_t addr, uint32_t& r0, uint32_t& r1,
                                        uint32_t& r2, uint32_t& r3) {
    asm volatile("ldmatrix.sync.aligned.m8n8.x4.shared.b16 {%0,%1,%2,%3}, [%4];"
                 : "=r"(r0), "=r"(r1), "=r"(r2), "=r"(r3) : "r"(addr));
}
__device__ __forceinline__ void mma16816f(float* d, const uint32_t* a, const uint32_t* b) {
    asm volatile(
        "mma.sync.aligned.m16n8k16.row.col.f32.f16.f16.f32 "
        "{%0,%1,%2,%3}, {%4,%5,%6,%7}, {%8,%9}, {%0,%1,%2,%3};"
        : "+f"(d[0]), "+f"(d[1]), "+f"(d[2]), "+f"(d[3])
        : "r"(a[0]), "r"(a[1]), "r"(a[2]), "r"(a[3]), "r"(b[0]), "r"(b[1]));
}
__device__ __forceinline__ void cpa16(uint32_t dst, const void* src) {
    asm volatile("cp.async.cg.shared.global [%0], [%1], 16;"
                 :: "r"(dst), "l"(src));
}
#define CP_COMMIT asm volatile("cp.async.commit_group;" ::: "memory")
#define CP_WAIT(n) asm volatile("cp.async.wait_group %0;" :: "n"(n) : "memory")

// ================= device scratch =================
__device__ __align__(16) float   g_X[NN * DD];          // fp32 (self term + pool)
__device__ __align__(16) __half  g_Xf16[NN * DD];       // fp16 copy for gather
__device__ __align__(16) __half  g_Hf[NN * DD];         // MLP input (fp16)
__device__ __align__(16) __half  g_etab_h[LL * 512 * DD];
__device__ int   g_rowptr[NN + 1];
__device__ int   g_deg[NN];
__device__ int   g_cursor[NN];
__device__ int   g_csr[EE];
__device__ __align__(16) __half  g_w1f[LL * 256 * 128];
__device__ __align__(16) __half  g_w2f[LL * 2 * 128 * 128];

// ================= fused preprocessing (zero + atom + etab + wconv) =========
#define PRE_ZERO   157
#define PRE_ATOM   (PRE_ZERO + 20000)
#define PRE_ETAB   (PRE_ATOM + 1280)
#define PRE_W1     (PRE_ETAB + 640)
#define PRE_TOTAL  (PRE_W1 + 640)

__global__ void k_pre(const int* __restrict__ xa, const float* __restrict__ aemb,
                      const float* __restrict__ bemb,
                      const float* __restrict__ W1, const float* __restrict__ W2) {
    int b = blockIdx.x;
    int tid = threadIdx.x;
    if (b < PRE_ZERO) {
        int i = b * 256 + tid;
        if (i < NN) { g_deg[i] = 0; g_cursor[i] = 0; }
    } else if (b < PRE_ATOM) {
        int node = (b - PRE_ZERO) * 2 + (tid >> 7);
        int d = tid & 127;
        float s = 0.f;
        #pragma unroll
        for (int f = 0; f < 9; ++f) {
            int idx = xa[node * 9 + f];
            s += aemb[(f * 64 + idx) * DD + d];
        }
        g_X[node * DD + d] = s;
        g_Xf16[node * DD + d] = __float2half_rn(s);
    } else if (b < PRE_ETAB) {
        int code = (b - PRE_ATOM) * 2 + (tid >> 7);
        int lay = code >> 9;
        int c = code & 511;
        int d = tid & 127;
        const float* bb = bemb + (size_t)lay * 3 * 8 * DD;
        float s = 0.f;
        #pragma unroll
        for (int f = 0; f < 3; ++f) {
            int idx = (c >> (3 * f)) & 7;
            s += bb[(f * 8 + idx) * DD + d];
        }
        g_etab_h[((size_t)lay * 512 + c) * DD + d] = __float2half_rn(s);
    } else if (b < PRE_W1) {
        int idx = (b - PRE_ETAB) * 256 + tid;
        int e = idx & 32767, l = idx >> 15;
        int n = e >> 7, k = e & 127;
        float v = W1[((size_t)l * 128 + k) * 256 + n];
        g_w1f[(size_t)l * 32768 + n * 128 + k] = __float2half_rn(v);
    } else {
        int idx = (b - PRE_W1) * 256 + tid;
        int e = idx & 16383, c = (idx >> 14) & 1, l = idx >> 15;
        int n = e >> 7, kk = e & 127;
        float v = W2[((size_t)l * 256 + c * 128 + kk) * 128 + n];
        g_w2f[((size_t)(l * 2 + c)) * 16384 + n * 128 + kk] = __float2half_rn(v);
    }
}

// ================= CSR construction =================
__global__ void k_count(const int* __restrict__ eidx) {
    int e = blockIdx.x * blockDim.x + threadIdx.x;
    if (e < EE) atomicAdd(&g_deg[eidx[EE + e]], 1);
}
__global__ void k_scan() {
    __shared__ int warp_sums[32];
    __shared__ int s_carry;
    int tid = threadIdx.x;
    if (tid == 0) { s_carry = 0; g_rowptr[0] = 0; }
    __syncthreads();
    int lane = tid & 31, w = tid >> 5;
    for (int base = 0; base < NN; base += 1024) {
        int i = base + tid;
        int v = (i < NN) ? g_deg[i] : 0;
        int x = v;
        #pragma unroll
        for (int o = 1; o < 32; o <<= 1) {
            int y = __shfl_up_sync(0xFFFFFFFFu, x, o);
            if (lane >= o) x += y;
        }
        if (lane == 31) warp_sums[w] = x;
        __syncthreads();
        if (w == 0) {
            int s = warp_sums[lane];
            #pragma unroll
            for (int o = 1; o < 32; o <<= 1) {
                int y = __shfl_up_sync(0xFFFFFFFFu, s, o);
                if (lane >= o) s += y;
            }
            warp_sums[lane] = s;
        }
        __syncthreads();
        int incl = x + (w > 0 ? warp_sums[w - 1] : 0) + s_carry;
        if (i < NN) g_rowptr[i + 1] = incl;
        __syncthreads();
        if (tid == 1023) s_carry = incl;
        __syncthreads();
    }
}
__global__ void k_fill(const int* __restrict__ eidx, const int* __restrict__ eattr) {
    int e = blockIdx.x * blockDim.x + threadIdx.x;
    if (e < EE) {
        int d = eidx[EE + e];
        int pos = atomicAdd(&g_cursor[d], 1);
        int s = eidx[e];
        int code = eattr[e * 3] | (eattr[e * 3 + 1] << 3) | (eattr[e * 3 + 2] << 6);
        g_csr[g_rowptr[d] + pos] = s | (code << 16);
    }
}

// ================= aggregate: half-warp/edge, LDG.128 gather ================
// Lane l: half = l>>4 (which edge of the pair), sub = l&15 (dims [sub*8, sub*8+8)).
// Each lane accumulates 8 dims in fp32; halves split even/odd edges; final
// shfl_xor(16) combine. Step-pairing in fp16 before cvt (validated R12).
__global__ void k_agg(const float* __restrict__ epsv, int layer) {
    int wid = threadIdx.x >> 5;
    int node = blockIdx.x * 8 + wid;
    int l = threadIdx.x & 31;
    int half = l >> 4;
    int sub = l & 15;
    const uint4* __restrict__ XH4 = (const uint4*)g_Xf16;
    const uint4* __restrict__ E4 = ((const uint4*)g_etab_h) + (size_t)layer * 512 * 16;
    const __half2 hz = __float2half2_rn(0.f);

    float acc[8];
    if (half == 0) {
        float eps1 = 1.f + epsv[layer];
        const float4* X4 = (const float4*)g_X;
        float4 a = X4[node * 32 + sub * 2];
        float4 b = X4[node * 32 + sub * 2 + 1];
        acc[0] = a.x * eps1; acc[1] = a.y * eps1; acc[2] = a.z * eps1; acc[3] = a.w * eps1;
        acc[4] = b.x * eps1; acc[5] = b.y * eps1; acc[6] = b.z * eps1; acc[7] = b.w * eps1;
    } else {
        #pragma unroll
        for (int q = 0; q < 8; ++q) acc[q] = 0.f;
    }

    int beg = g_rowptr[node], end = g_rowptr[node + 1];
    int j = beg;
    // 2 steps per iter = 4 edges: 2 csr + 4 LDG.128, fp16 step-pair combine
    for (; j + 3 < end; j += 4) {
        int pA = g_csr[j + half];
        int pB = g_csr[j + 2 + half];
        uint4 xA = XH4[(pA & 0xFFFF) * 16 + sub];
        uint4 eA = E4[(pA >> 16) * 16 + sub];
        uint4 xB = XH4[(pB & 0xFFFF) * 16 + sub];
        uint4 eB = E4[(pB >> 16) * 16 + sub];
        __half2 s0 = __hadd2(__hmax2(__hadd2(*(__half2*)&xA.x, *(__half2*)&eA.x), hz),
                             __hmax2(__hadd2(*(__half2*)&xB.x, *(__half2*)&eB.x), hz));
        __half2 s1 = __hadd2(__hmax2(__hadd2(*(__half2*)&xA.y, *(__half2*)&eA.y), hz),
                             __hmax2(__hadd2(*(__half2*)&xB.y, *(__half2*)&eB.y), hz));
        __half2 s2 = __hadd2(__hmax2(__hadd2(*(__half2*)&xA.z, *(__half2*)&eA.z), hz),
                             __hmax2(__hadd2(*(__half2*)&xB.z, *(__half2*)&eB.z), hz));
        __half2 s3 = __hadd2(__hmax2(__hadd2(*(__half2*)&xA.w, *(__half2*)&eA.w), hz),
                             __hmax2(__hadd2(*(__half2*)&xB.w, *(__half2*)&eB.w), hz));
        float2 f0 = __half22float2(s0), f1 = __half22float2(s1);
        float2 f2 = __half22float2(s2), f3 = __half22float2(s3);
        acc[0] += f0.x; acc[1] += f0.y; acc[2] += f1.x; acc[3] += f1.y;
        acc[4] += f2.x; acc[5] += f2.y; acc[6] += f3.x; acc[7] += f3.y;
    }
    if (j + 1 < end) {   // one step = 2 edges (one per half)
        int p = g_csr[j + half];
        uint4 x = XH4[(p & 0xFFFF) * 16 + sub];
        uint4 e = E4[(p >> 16) * 16 + sub];
        __half2 m0 = __hmax2(__hadd2(*(__half2*)&x.x, *(__half2*)&e.x), hz);
        __half2 m1 = __hmax2(__hadd2(*(__half2*)&x.y, *(__half2*)&e.y), hz);
        __half2 m2 = __hmax2(__hadd2(*(__half2*)&x.z, *(__half2*)&e.z), hz);
        __half2 m3 = __hmax2(__hadd2(*(__half2*)&x.w, *(__half2*)&e.w), hz);
        float2 f0 = __half22float2(m0), f1 = __half22float2(m1);
        float2 f2 = __half22float2(m2), f3 = __half22float2(m3);
        acc[0] += f0.x; acc[1] += f0.y; acc[2] += f1.x; acc[3] += f1.y;
        acc[4] += f2.x; acc[5] += f2.y; acc[6] += f3.x; acc[7] += f3.y;
        j += 2;
    }
    if (j < end && half == 0) {   // final single edge: half 0 only
        int p = g_csr[j];
        uint4 x = XH4[(p & 0xFFFF) * 16 + sub];
        uint4 e = E4[(p >> 16) * 16 + sub];
        __half2 m0 = __hmax2(__hadd2(*(__half2*)&x.x, *(__half2*)&e.x), hz);
        __half2 m1 = __hmax2(__hadd2(*(__half2*)&x.y, *(__half2*)&e.y), hz);
        __half2 m2 = __hmax2(__hadd2(*(__half2*)&x.z, *(__half2*)&e.z), hz);
        __half2 m3 = __hmax2(__hadd2(*(__half2*)&x.w, *(__half2*)&e.w), hz);
        float2 f0 = __half22float2(m0), f1 = __half22float2(m1);
        float2 f2 = __half22float2(m2), f3 = __half22float2(m3);
        acc[0] += f0.x; acc[1] += f0.y; acc[2] += f1.x; acc[3] += f1.y;
        acc[4] += f2.x; acc[5] += f2.y; acc[6] += f3.x; acc[7] += f3.y;
    }
    // cross-half combine
    #pragma unroll
    for (int q = 0; q < 8; ++q)
        acc[q] += __shfl_xor_sync(0xFFFFFFFFu, acc[q], 16);
    if (half == 0) {
        uint4 outv;
        *(__half2*)&outv.x = __floats2half2_rn(acc[0], acc[1]);
        *(__half2*)&outv.y = __floats2half2_rn(acc[2], acc[3]);
        *(__half2*)&outv.z = __floats2half2_rn(acc[4], acc[5]);
        *(__half2*)&outv.w = __floats2half2_rn(acc[6], acc[7]);
        ((uint4*)g_Hf)[node * 16 + sub] = outv;
    }
}

// ================= fused MLP: H[64x128] -> M[64x256] (smem) -> X[64x128] =====
#define SM_A   0
#define SM_W1  16384
#define SM_M0  81920
#define SM_M1  98304
#define SM_W2A 0
#define SM_W2B 32768
#define MLP_SMEM 114688

__device__ __forceinline__ void stage_tile(const __half* __restrict__ src,
                                           int row0, int nrows, int rowstride,
                                           int k0, uint32_t sdst, int tid) {
    for (int it = tid; it < nrows * 16; it += 256) {
        int r = it >> 4, ci = it & 15;
        size_t gofs = (size_t)(row0 + r) * rowstride + k0 + ci * 8;
        uint32_t off = (uint32_t)(r * 256 + ((ci ^ (r & 7)) << 4));
        cpa16(sdst + off, src + gofs);
    }
}

template<int NJT>
__device__ __forceinline__ void gemm_chunk_f16(
    uint32_t a_base, uint32_t b_base,
    int a_lrow, int a_x7, int a_lci, int b_nrow, int b_x7, int b_lci,
    float (&acc)[2][NJT][4])
{
    #pragma unroll
    for (int s = 0; s < 8; ++s) {
        uint32_t a[2][4], b[NJT][2];
        uint32_t acn = (uint32_t)(((s << 1) | a_lci) ^ a_x7);
        #pragma unroll
        for (int i = 0; i < 2; ++i) {
            uint32_t addr = a_base + (a_lrow + i * 16) * 256 + (acn << 4);
            ldsm_x4(addr, a[i][0], a[i][1], a[i][2], a[i][3]);
        }
        uint32_t bcn = (uint32_t)(((s << 1) | b_lci) ^ b_x7);
        #pragma unroll
        for (int p = 0; p < NJT / 2; ++p) {
            uint32_t addr = b_base + (b_nrow + p * 16) * 256 + (bcn << 4);
            uint32_t r0, r1, r2, r3;
            ldsm_x4(addr, r0, r1, r2, r3);
            b[2 * p][0] = r0; b[2 * p][1] = r1;
            b[2 * p + 1][0] = r2; b[2 * p + 1][1] = r3;
        }
        #pragma unroll
        for (int i = 0; i < 2; ++i)
            #pragma unroll
            for (int j = 0; j < NJT; ++j)
                mma16816f(acc[i][j], a[i], b[j]);
    }
}

__global__ void __launch_bounds__(256, 2) k_mlp(
    int layer,
    const float* __restrict__ b1,  const float* __restrict__ g1,
    const float* __restrict__ bt1, const float* __restrict__ m1,
    const float* __restrict__ v1,
    const float* __restrict__ b2,  const float* __restrict__ gO,
    const float* __restrict__ btO, const float* __restrict__ mO,
    const float* __restrict__ vO,
    int relu_flag)
{
    extern __shared__ char smem[];
    uint32_t sbase = smem_u32(smem);
    int tid = threadIdx.x, lane = tid & 31, wid = tid >> 5;
    int wm = wid >> 2, wn = wid & 3;
    int m0 = blockIdx.x * 64;

    int a_lrow = wm * 32 + (lane & 15);
    int a_x7 = a_lrow & 7;
    int a_lci = lane >> 4;
    int b1_nrow = wn * 64 + ((lane >> 4) << 3) + (lane & 7);
    int b1_x7 = b1_nrow & 7;
    int b1_lci = (lane >> 3) & 1;
    int b2_nrow = wn * 32 + ((lane >> 4) << 3) + (lane & 7);
    int b2_x7 = b2_nrow & 7;
    int b2_lci = (lane >> 3) & 1;

    stage_tile(g_Hf, m0, 64, 128, 0, sbase + SM_A, tid);
    stage_tile(g_w1f + (size_t)layer * 32768, 0, 256, 128, 0, sbase + SM_W1, tid);
    CP_COMMIT;

    float acc1[2][8][4];
    #pragma unroll
    for (int i = 0; i < 2; ++i)
        #pragma unroll
        for (int j = 0; j < 8; ++j)
            #pragma unroll
            for (int q = 0; q < 4; ++q) acc1[i][j][q] = 0.f;

    CP_WAIT(0); __syncthreads();
    gemm_chunk_f16<8>(sbase + SM_A, sbase + SM_W1,
                      a_lrow, a_x7, a_lci, b1_nrow, b1_x7, b1_lci, acc1);
    __syncthreads();

    const __half* wimg2 = g_w2f + (size_t)layer * 2 * 16384;
    stage_tile(wimg2, 0, 128, 128, 0, sbase + SM_W2A, tid);
    stage_tile(wimg2 + 16384, 0, 128, 128, 0, sbase + SM_W2B, tid);
    CP_COMMIT;

    #pragma unroll
    for (int i = 0; i < 2; ++i) {
        int rl0 = wm * 32 + i * 16 + (lane >> 2);
        #pragma unroll
        for (int j = 0; j < 8; ++j) {
            int lc = wn * 64 + j * 8 + (lane & 3) * 2;
            float sc0 = __ldg(&g1[lc])     * rsqrtf(__ldg(&v1[lc]) + 1e-5f);
            float sc1 = __ldg(&g1[lc + 1]) * rsqrtf(__ldg(&v1[lc + 1]) + 1e-5f);
            float sb0 = __ldg(&bt1[lc])     + (__ldg(&b1[lc])     - __ldg(&m1[lc]))     * sc0;
            float sb1 = __ldg(&bt1[lc + 1]) + (__ldg(&b1[lc + 1]) - __ldg(&m1[lc + 1])) * sc1;
            int mbase = (lc >> 7) ? SM_M1 : SM_M0;
            int lcl = lc & 127;
            int ci = lcl >> 3;
            int sub = (lcl & 7) * 2;
            #pragma unroll
            for (int h = 0; h < 2; ++h) {
                int r = rl0 + h * 8;
                float v0 = fmaxf(acc1[i][j][2 * h]     * sc0 + sb0, 0.f);
                float v1v = fmaxf(acc1[i][j][2 * h + 1] * sc1 + sb1, 0.f);
                uint32_t off = (uint32_t)(mbase + r * 256 + ((ci ^ (r & 7)) << 4) + sub);
                *(__half2*)(smem + off) = __floats2half2_rn(v0, v1v);
            }
        }
    }
    CP_WAIT(0); __syncthreads();

    float acc2[2][4][4];
    #pragma unroll
    for (int i = 0; i < 2; ++i)
        #pragma unroll
        for (int j = 0; j < 4; ++j)
            #pragma unroll
            for (int q = 0; q < 4; ++q) acc2[i][j][q] = 0.f;

    gemm_chunk_f16<4>(sbase + SM_M0, sbase + SM_W2A,
                      a_lrow, a_x7, a_lci, b2_nrow, b2_x7, b2_lci, acc2);
    gemm_chunk_f16<4>(sbase + SM_M1, sbase + SM_W2B,
                      a_lrow, a_x7, a_lci, b2_nrow, b2_x7, b2_lci, acc2);

    #pragma unroll
    for (int i = 0; i < 2; ++i) {
        int row0 = m0 + wm * 32 + i * 16 + (lane >> 2);
        #pragma unroll
        for (int j = 0; j < 4; ++j) {
            int lc = wn * 32 + j * 8 + (lane & 3) * 2;
            float sc0 = __ldg(&gO[lc])     * rsqrtf(__ldg(&vO[lc]) + 1e-5f);
            float sc1 = __ldg(&gO[lc + 1]) * rsqrtf(__ldg(&vO[lc + 1]) + 1e-5f);
            float sb0 = __ldg(&btO[lc])     + (__ldg(&b2[lc])     - __ldg(&mO[lc]))     * sc0;
            float sb1 = __ldg(&btO[lc + 1]) + (__ldg(&b2[lc + 1]) - __ldg(&mO[lc + 1])) * sc1;
            #pragma unroll
            for (int h = 0; h < 2; ++h) {
                int row = row0 + h * 8;
                float v0 = acc2[i][j][2 * h]     * sc0 + sb0;
                float v1v = acc2[i][j][2 * h + 1] * sc1 + sb1;
                if (relu_flag) { v0 = fmaxf(v0, 0.f); v1v = fmaxf(v1v, 0.f); }
                size_t ob = (size_t)row * 128 + lc;
                *(float2*)(g_X + ob) = make_float2(v0, v1v);
                *(__half2*)(g_Xf16 + ob) = __floats2half2_rn(v0, v1v);
            }
        }
    }
}

// ================= pooling + head =================
__device__ __forceinline__ int lb(const int* a, int n, int v) {
    int lo = 0, hi = n;
    while (lo < hi) { int m = (lo + hi) >> 1; if (a[m] < v) lo = m + 1; else hi = m; }
    return lo;
}
__global__ void k_pool(const int* __restrict__ batch,
                       const float* __restrict__ Wp, const float* __restrict__ bp,
                       float* __restrict__ out)
{
    int g = blockIdx.x;
    int lo = lb(batch, NN, g);
    int hi = lb(batch, NN, g + 1);
    int d = threadIdx.x;
    float s = 0.f;
    for (int n = lo; n < hi; ++n) s += g_X[n * DD + d];
    s /= fmaxf((float)(hi - lo), 1.f);
    __shared__ float pooled[DD];
    pooled[d] = s;
    __syncthreads();
    if (d < 10) {
        float o = bp[d];
        #pragma unroll 4
        for (int k = 0; k < DD; ++k) o += pooled[k] * Wp[k * 10 + d];
        out[g * 10 + d] = o;
    }
}

// ================= launch =================
extern "C" void kernel_launch(void* const* d_in, const int* in_sizes, int n_in,
                              void* d_out, int out_size)
{
    const int*   x_atom = (const int*)d_in[0];
    const int*   eidx   = (const int*)d_in[1];
    const int*   eattr  = (const int*)d_in[2];
    const int*   batch  = (const int*)d_in[3];
    const float* aemb   = (const float*)d_in[4];
    const float* bemb   = (const float*)d_in[5];
    const float* eps    = (const float*)d_in[6];
    const float* W1     = (const float*)d_in[7];
    const float* b1     = (const float*)d_in[8];
    const float* g1     = (const float*)d_in[9];
    const float* bt1    = (const float*)d_in[10];
    const float* m1     = (const float*)d_in[11];
    const float* v1     = (const float*)d_in[12];
    const float* W2     = (const float*)d_in[13];
    const float* b2     = (const float*)d_in[14];
    const float* gO     = (const float*)d_in[15];
    const float* btO    = (const float*)d_in[16];
    const float* mO     = (const float*)d_in[17];
    const float* vO     = (const float*)d_in[18];
    const float* Wp     = (const float*)d_in[19];
    const float* bp     = (const float*)d_in[20];
    float* out = (float*)d_out;

    cudaFuncSetAttribute(k_mlp, cudaFuncAttributeMaxDynamicSharedMemorySize, MLP_SMEM);

    k_pre<<<PRE_TOTAL, 256>>>(x_atom, aemb, bemb, W1, W2);
    k_count<<<(EE + 255) / 256, 256>>>(eidx);
    k_scan<<<1, 1024>>>();
    k_fill<<<(EE + 255) / 256, 256>>>(eidx, eattr);

    for (int i = 0; i < LL; ++i) {
        k_agg<<<NN / 8, 256>>>(eps, i);
        k_mlp<<<625, 256, MLP_SMEM>>>(i,
            b1 + i * 2 * DD, g1 + i * 2 * DD, bt1 + i * 2 * DD,
            m1 + i * 2 * DD, v1 + i * 2 * DD,
            b2 + i * DD, gO + i * DD, btO + i * DD,
            mO + i * DD, vO + i * DD, (i < LL - 1) ? 1 : 0);
    }

    k_pool<<<GG, 128>>>(batch, Wp, bp, out);
}